// round 15
// baseline (speedup 1.0000x reference)
#include <cuda_runtime.h>
#include <math.h>

#define HW   65536
#define IMG  6291456          // 96*65536
#define NPIX 25165824         // 4*96*65536
#define SCALE 0.17677669529663687f

typedef unsigned long long ull;

// Full-batch buffers. g_Q / g_K are reused as D0 / D1 scratch after attention.
static __device__ __align__(16) float g_V[NPIX];
static __device__ __align__(16) float g_aV[NPIX];
static __device__ __align__(16) float g_Q[NPIX];
static __device__ __align__(16) float g_K[NPIX];
static __device__ __align__(16) float g_attn[NPIX];
static __device__ __align__(16) float g_bias[3 * 64 * 64];

// ---- f32x2 packed helpers (attention) --------------------------------------
__device__ __forceinline__ ull pk(float x) {
    ull r; asm("mov.b64 %0, {%1, %1};" : "=l"(r) : "f"(x)); return r;
}
__device__ __forceinline__ ull pk2(float lo, float hi) {
    ull r; asm("mov.b64 %0, {%1, %2};" : "=l"(r) : "f"(lo), "f"(hi)); return r;
}
__device__ __forceinline__ float2 upk(ull v) {
    float2 f; asm("mov.b64 {%0, %1}, %2;" : "=f"(f.x), "=f"(f.y) : "l"(v)); return f;
}
__device__ __forceinline__ ull fma2(ull a, ull b, ull c) {
    ull r; asm("fma.rn.f32x2 %0, %1, %2, %3;" : "=l"(r) : "l"(a), "l"(b), "l"(c)); return r;
}
__device__ __forceinline__ ull add2(ull a, ull b) {
    ull r; asm("add.rn.f32x2 %0, %1, %2;" : "=l"(r) : "l"(a), "l"(b)); return r;
}
__device__ __forceinline__ ull mul2(ull a, ull b) {
    ull r; asm("mul.rn.f32x2 %0, %1, %2;" : "=l"(r) : "l"(a), "l"(b)); return r;
}

// ---- mma.sync helpers -------------------------------------------------------
__device__ __forceinline__ unsigned smem_u32(const void* p) {
    unsigned a;
    asm("{ .reg .u64 t; cvta.to.shared.u64 t, %1; cvt.u32.u64 %0, t; }" : "=r"(a) : "l"(p));
    return a;
}
__device__ __forceinline__ void ldsm4(unsigned* r, unsigned addr) {
    asm volatile("ldmatrix.sync.aligned.m8n8.x4.shared.b16 {%0,%1,%2,%3}, [%4];"
                 : "=r"(r[0]), "=r"(r[1]), "=r"(r[2]), "=r"(r[3]) : "r"(addr));
}
__device__ __forceinline__ void mma_bf16(float* c, const unsigned* a, unsigned b0, unsigned b1) {
    asm volatile(
        "mma.sync.aligned.m16n8k16.row.col.f32.bf16.bf16.f32 "
        "{%0,%1,%2,%3}, {%4,%5,%6,%7}, {%8,%9}, {%0,%1,%2,%3};"
        : "+f"(c[0]), "+f"(c[1]), "+f"(c[2]), "+f"(c[3])
        : "r"(a[0]), "r"(a[1]), "r"(a[2]), "r"(a[3]), "r"(b0), "r"(b1));
}
// pack 2 floats -> bf16x2 {lo=v0, hi=v1}
__device__ __forceinline__ unsigned cvt2(float v0, float v1) {
    unsigned r; asm("cvt.rn.bf16x2.f32 %0, %1, %2;" : "=r"(r) : "f"(v1), "f"(v0)); return r;
}

// swizzled smem byte offsets: row stride 384 B, 16B-window XOR by (row&7)
__device__ __forceinline__ int physA(int px, int kb) { return px * 384 + (kb ^ ((px & 7) << 4)); }
__device__ __forceinline__ int physB(int o,  int kb) { return o  * 384 + (kb ^ ((o  & 7) << 4)); }

#define SM_A 0
#define SM_B 49152
#define SM_BIAS 86016
#define SM_TOTAL 87424

// ---------------------------------------------------------------------------
// K1: relative-position bias MLP
// ---------------------------------------------------------------------------
__device__ __forceinline__ float sgnlog(int d) {
    float l = log1pf(fabsf((float)d));
    return d < 0 ? -l : l;
}

__global__ void bias_kernel(const float* __restrict__ mw1, const float* __restrict__ mb1,
                            const float* __restrict__ mw2, const float* __restrict__ mb2) {
    int t = blockIdx.x * 256 + threadIdx.x;
    if (t >= 4096) return;
    int i = t >> 6, j = t & 63;
    float r0 = sgnlog((i >> 3) - (j >> 3));
    float r1 = sgnlog((i & 7) - (j & 7));
    float a0 = 0.f, a1 = 0.f, a2 = 0.f;
    for (int h = 0; h < 256; h++) {
        float hid = fmaf(r0, mw1[h], fmaf(r1, mw1[256 + h], mb1[h]));
        hid = fmaxf(hid, 0.f);
        a0 = fmaf(hid, mw2[h * 3 + 0], a0);
        a1 = fmaf(hid, mw2[h * 3 + 1], a1);
        a2 = fmaf(hid, mw2[h * 3 + 2], a2);
    }
    g_bias[t]        = a0 + mb2[0];
    g_bias[4096 + t] = a1 + mb2[1];
    g_bias[8192 + t] = a2 + mb2[2];
}

// ---------------------------------------------------------------------------
// Shared conv building blocks (mma.sync bf16 split-2)
// ---------------------------------------------------------------------------
__device__ __forceinline__ void conv_a_convert(char* raw, const float* inb, int wid, int lane) {
    int c2 = lane >> 3, pxl = lane & 7;   // 4 c-pairs x 8 px per warp-iter
    #pragma unroll 4
    for (int it = 0; it < 24; it++) {
        int g = it * 8 + wid;             // 0..191
        int po = g & 15, cq = g >> 4;     // 16 px-octets x 12 c-quads
        int c = cq * 8 + c2 * 2;
        int px = po * 8 + pxl;
        float v0 = inb[c * HW + px];
        float v1 = inb[(c + 1) * HW + px];
        unsigned hi = cvt2(v0, v1);
        float h0 = __uint_as_float(hi << 16);
        float h1 = __uint_as_float(hi & 0xffff0000u);
        unsigned lo = cvt2(v0 - h0, v1 - h1);
        *(unsigned*)(raw + SM_A + physA(px, c * 2))       = hi;
        *(unsigned*)(raw + SM_A + physA(px, 192 + c * 2)) = lo;
    }
}

__device__ __forceinline__ void conv_b_convert(char* raw, const float* w, int tid) {
    for (int l = tid; l < 4608; l += 256) {
        int o = l / 48, cp = l - (l / 48) * 48;
        int c = cp * 2;
        float2 wv = upk(*(const ull*)(w + o * 96 + c));
        unsigned hi = cvt2(wv.x, wv.y);
        float h0 = __uint_as_float(hi << 16);
        float h1 = __uint_as_float(hi & 0xffff0000u);
        unsigned lo = cvt2(wv.x - h0, wv.y - h1);
        *(unsigned*)(raw + SM_B + physB(o, c * 2))       = hi;
        *(unsigned*)(raw + SM_B + physB(o, 192 + c * 2)) = lo;
    }
}

// mainloop + epilogue. Caller must __syncthreads() before (B ready).
__device__ __forceinline__ void conv_mma_epi(
    char* raw, const float* s_bias_p, float* outb, float scl,
    int wid, int lane)
{
    unsigned sA32 = smem_u32(raw + SM_A);
    unsigned sB32 = smem_u32(raw + SM_B);
    int wm = wid >> 1, wn = wid & 1;
    int gr = lane & 7, gi = lane >> 3;
    int swz = gr << 4;
    int kextA = (gi >> 1) << 4;   // bytes
    int kextB = (gi & 1) << 4;
    int aRow[2], bRow[3];
    #pragma unroll
    for (int tm = 0; tm < 2; tm++)
        aRow[tm] = (wm * 32 + tm * 16 + gr + (gi & 1) * 8) * 384;
    #pragma unroll
    for (int tp = 0; tp < 3; tp++)
        bRow[tp] = (wn * 48 + tp * 16 + gr + (gi >> 1) * 8) * 384;

    float c[2][6][4];
    #pragma unroll
    for (int tm = 0; tm < 2; tm++)
        #pragma unroll
        for (int tn = 0; tn < 6; tn++)
            #pragma unroll
            for (int q = 0; q < 4; q++) c[tm][tn][q] = 0.f;

    #pragma unroll
    for (int t = 0; t < 3; t++) {
        int kaB = (t == 2) ? 192 : 0;     // A lo for term 2
        int kbB = (t == 1) ? 192 : 0;     // B lo for term 1
        #pragma unroll
        for (int ks = 0; ks < 6; ks++) {
            unsigned aF[2][4], bF[3][4];
            int ka = kaB + ks * 32;
            int kb = kbB + ks * 32;
            #pragma unroll
            for (int tm = 0; tm < 2; tm++)
                ldsm4(aF[tm], sA32 + aRow[tm] + ((ka + kextA) ^ swz));
            #pragma unroll
            for (int tp = 0; tp < 3; tp++)
                ldsm4(bF[tp], sB32 + bRow[tp] + ((kb + kextB) ^ swz));
            #pragma unroll
            for (int tm = 0; tm < 2; tm++)
                #pragma unroll
                for (int tn = 0; tn < 6; tn++) {
                    int tp = tn >> 1, r0 = (tn & 1) * 2;
                    mma_bf16(c[tm][tn], aF[tm], bF[tp][r0], bF[tp][r0 + 1]);
                }
        }
    }
    __syncthreads();   // all ldsm done -> B buffer reusable by caller

    int pr = lane >> 2, oc = (lane & 3) * 2;
    #pragma unroll
    for (int tm = 0; tm < 2; tm++) {
        int pxr = wm * 32 + tm * 16 + pr;
        #pragma unroll
        for (int tn = 0; tn < 6; tn++) {
            int o0 = wn * 48 + tn * 8 + oc;
            float b0 = s_bias_p[o0], b1 = s_bias_p[o0 + 1];
            outb[o0 * HW + pxr]            = (c[tm][tn][0] + b0) * scl;
            outb[(o0 + 1) * HW + pxr]      = (c[tm][tn][1] + b1) * scl;
            outb[o0 * HW + pxr + 8]        = (c[tm][tn][2] + b0) * scl;
            outb[(o0 + 1) * HW + pxr + 8]  = (c[tm][tn][3] + b1) * scl;
        }
    }
}

// ---------------------------------------------------------------------------
// K2a: phased V/Q/K conv1x1 — one A conversion, three B phases. grid 2048.
// ---------------------------------------------------------------------------
__global__ __launch_bounds__(256, 2)
void conv3_kernel(const float* __restrict__ vision,
                  const float* __restrict__ wv,  const float* __restrict__ bv,
                  const float* __restrict__ wqk, const float* __restrict__ bqk) {
    extern __shared__ __align__(16) char raw[];
    float* s_bias = (float*)(raw + SM_BIAS);

    int tid = threadIdx.x;
    int wid = tid >> 5, lane = tid & 31;
    int bx = blockIdx.x;
    int b = bx >> 9, px0 = (bx & 511) << 7;
    const float* inb = vision + b * IMG + px0;
    int gbase = b * IMG + px0;

    // all three bias vectors up front
    if (tid < 96)        s_bias[tid]        = bv[tid];
    else if (tid < 192)  s_bias[tid]        = bqk[tid - 96];        // Q bias at +96
    if (tid < 96)        s_bias[192 + tid]  = bqk[96 + tid];        // K bias at +192

    conv_a_convert(raw, inb, wid, lane);

    // phase 0: V
    conv_b_convert(raw, wv, tid);
    __syncthreads();
    conv_mma_epi(raw, s_bias, g_V + gbase, 1.0f, wid, lane);

    // phase 1: Q (pre-scaled)
    conv_b_convert(raw, wqk, tid);
    __syncthreads();
    conv_mma_epi(raw, s_bias + 96, g_Q + gbase, SCALE, wid, lane);

    // phase 2: K
    conv_b_convert(raw, wqk + 9216, tid);
    __syncthreads();
    conv_mma_epi(raw, s_bias + 192, g_K + gbase, 1.0f, wid, lane);
}

// ---------------------------------------------------------------------------
// K2b: generic single-job conv1x1.
// ---------------------------------------------------------------------------
struct ConvJob { const float* in; const float* w; const float* bias; float* out; float scale; };

__global__ __launch_bounds__(256, 2)
void conv_kernel(ConvJob j) {
    extern __shared__ __align__(16) char raw[];
    float* s_bias = (float*)(raw + SM_BIAS);

    int tid = threadIdx.x;
    int wid = tid >> 5, lane = tid & 31;
    int bx = blockIdx.x;
    int b = bx >> 9, px0 = (bx & 511) << 7;
    const float* inb = j.in + b * IMG + px0;

    if (tid < 96) s_bias[tid] = j.bias[tid];
    conv_a_convert(raw, inb, wid, lane);
    conv_b_convert(raw, j.w, tid);
    __syncthreads();
    conv_mma_epi(raw, s_bias, j.out + b * IMG + px0, j.scale, wid, lane);
}

// ---------------------------------------------------------------------------
// K3: window attention — two threads per (head, row), blocked halves,
// LDS.128 K/V mainloop, d-major Q.
// smem bytes: Q d-major [h][d][n]   0..24576   (256 B per d-row)
//             K [h][d][36 ull]      24576..52224 (half0 @ ull 0, half1 @ ull 18)
//             V [h][m*36+d]         52224..79872 (pitch 144 B)
// ---------------------------------------------------------------------------
#define AQ_B 0
#define AK_B 24576
#define AV_B 52224
#define SMEM_ATTN 79872

__global__ __launch_bounds__(384, 2)
void attn_kernel() {
    extern __shared__ __align__(16) char rawc[];

    int tid = threadIdx.x;
    int blk = blockIdx.x;
    int b = blk >> 10, wy = (blk >> 5) & 31, wx = blk & 31;
    int pixoff = b * IMG + wy * 2048 + wx * 8;

    // ---- loader: coalesced gmem, q as packed ull (conflict-free), K 2-way,
    //      V scalar (8-way but only 2 stores/iter) ----
    for (int l = tid; l < 3072; l += 384) {
        int hh = l >> 10;
        int r = l & 1023;
        int d = r >> 5, n2 = r & 31;
        int ga = pixoff + (hh * 32 + d) * HW + (n2 >> 2) * 256 + (n2 & 3) * 2;
        float2 q = upk(*(const ull*)(g_Q + ga));
        *(ull*)(rawc + AQ_B + hh * 8192 + d * 256 + n2 * 8) = pk2(q.x, q.y);
        int ki = n2 + ((n2 >> 4) << 1);   // half1 block starts at ull 18
        *(ull*)(rawc + AK_B + hh * 9216 + d * 288 + ki * 8) = *(const ull*)(g_K + ga);
        float2 v = upk(*(const ull*)(g_V + ga));
        float* vb = (float*)(rawc + AV_B) + hh * 2304 + d;
        vb[(2 * n2) * 36]     = v.x;
        vb[(2 * n2 + 1) * 36] = v.y;
    }
    __syncthreads();

    int h = tid >> 7;                 // head
    int r = tid & 127;
    int n = r >> 1, half = r & 1;     // partner = lane^1
    const float* qd0 = (const float*)(rawc + AQ_B + h * 8192) + n;   // stride 64 f per d
    const char*  kh  = rawc + AK_B + h * 9216 + half * 144;          // my half block
    const float* vh  = (const float*)(rawc + AV_B) + h * 2304;

    // ---- S half-row: acc[jj] = scores for m2 = 16*half + jj ----
    ull acc[16];
    {
        const ull* bias2 = (const ull*)(g_bias + h * 4096 + n * 64) + 16 * half;
        #pragma unroll
        for (int jj = 0; jj < 16; jj++) acc[jj] = bias2[jj];
    }
    #pragma unroll 4
    for (int d = 0; d < 32; d++) {
        ull qd = pk(qd0[d * 64]);
        const ulonglong2* krow = (const ulonglong2*)(kh + d * 288);
        #pragma unroll
        for (int j2 = 0; j2 < 8; j2++) {
            ulonglong2 kk = krow[j2];
            acc[2 * j2]     = fma2(qd, kk.x, acc[2 * j2]);
            acc[2 * j2 + 1] = fma2(qd, kk.y, acc[2 * j2 + 1]);
        }
    }

    // ---- softmax across the pair ----
    float mx = -1e30f;
    #pragma unroll
    for (int jj = 0; jj < 16; jj++) {
        float2 f = upk(acc[jj]);
        mx = fmaxf(mx, fmaxf(f.x, f.y));
    }
    mx = fmaxf(mx, __shfl_xor_sync(0xffffffffu, mx, 1));
    float p[32];
    float sum = 0.f;
    #pragma unroll
    for (int jj = 0; jj < 16; jj++) {
        float2 f = upk(acc[jj]);
        p[2 * jj]     = __expf(f.x - mx);
        p[2 * jj + 1] = __expf(f.y - mx);
        sum += p[2 * jj] + p[2 * jj + 1];
    }
    sum += __shfl_xor_sync(0xffffffffu, sum, 1);
    float rinv = 1.f / sum;

    // ---- PV over my 32 columns (m in [32*half, 32*half+32)) ----
    const float* vmine  = vh + half * 16;
    const float* vother = vh + 16 - half * 16;
    ull oacc[16];
    #pragma unroll
    for (int d2 = 0; d2 < 16; d2++) oacc[d2] = 0ull;
    #pragma unroll 2
    for (int jj = 0; jj < 16; jj++) {
        int m0 = 32 * half + 2 * jj;
        ull pm0 = pk(p[2 * jj]), pm1 = pk(p[2 * jj + 1]);
        const char* a0 = (const char*)(vmine + m0 * 36);
        const char* b0 = (const char*)(vother + m0 * 36);
        #pragma unroll
        for (int g = 0; g < 4; g++) {
            ulonglong2 va = *(const ulonglong2*)(a0 + 16 * g);
            oacc[2 * g]     = fma2(pm0, va.x, oacc[2 * g]);
            oacc[2 * g + 1] = fma2(pm0, va.y, oacc[2 * g + 1]);
            ulonglong2 vb2 = *(const ulonglong2*)(b0 + 16 * g);
            oacc[8 + 2 * g]     = fma2(pm0, vb2.x, oacc[8 + 2 * g]);
            oacc[8 + 2 * g + 1] = fma2(pm0, vb2.y, oacc[8 + 2 * g + 1]);
        }
        #pragma unroll
        for (int g = 0; g < 4; g++) {
            ulonglong2 va = *(const ulonglong2*)(a0 + 144 + 16 * g);
            oacc[2 * g]     = fma2(pm1, va.x, oacc[2 * g]);
            oacc[2 * g + 1] = fma2(pm1, va.y, oacc[2 * g + 1]);
            ulonglong2 vb2 = *(const ulonglong2*)(b0 + 144 + 16 * g);
            oacc[8 + 2 * g]     = fma2(pm1, vb2.x, oacc[8 + 2 * g]);
            oacc[8 + 2 * g + 1] = fma2(pm1, vb2.y, oacc[8 + 2 * g + 1]);
        }
    }

    // ---- combine with partner: partner's oacc[8+k] is MY d-half ----
    #pragma unroll
    for (int k = 0; k < 8; k++) {
        ull recv = __shfl_xor_sync(0xffffffffu, oacc[8 + k], 1);
        oacc[k] = add2(oacc[k], recv);
    }

    // ---- scale + store my 16 d's ----
    ull rr = pk(rinv);
    float* obd = g_attn + pixoff + (n >> 3) * 256 + (n & 7) + (h * 32 + half * 16) * HW;
    #pragma unroll
    for (int k = 0; k < 8; k++) {
        float2 f = upk(mul2(oacc[k], rr));
        obd[(2 * k) * HW]     = f.x;
        obd[(2 * k + 1) * HW] = f.y;
    }
}

// ---------------------------------------------------------------------------
// K4: single-z depthwise 5x5 + bias + attn -> D. grid 6144 per z.
// ---------------------------------------------------------------------------
__global__ __launch_bounds__(256)
void dwz_kernel(const float* __restrict__ Vp, const float* __restrict__ wD,
                const float* __restrict__ bD, float* __restrict__ Dp) {
    extern __shared__ float st[];
    float* s_wd = st + 5280;           // halo [20][264] then weights

    int bx = blockIdx.x;               // 6144 = 16 * 96 * 4
    int yt = bx & 15;
    int v = bx >> 4;
    int c = v % 96, b = v / 96;
    int y0 = yt << 4;
    int tid = threadIdx.x;
    int chan = b * IMG + c * HW;
    const float* Vc = Vp + chan;

    for (int l = tid; l < 5200; l += 256) {
        int r = l / 260, q = l - r * 260;
        int yy = y0 + r - 2; yy = yy < 0 ? -yy : (yy > 255 ? 510 - yy : yy);
        int xx = q - 2;      xx = xx < 0 ? -xx : (xx > 255 ? 510 - xx : xx);
        st[r * 264 + q] = Vc[yy * 256 + xx];
    }
    if (tid < 25) s_wd[tid] = wD[c * 25 + tid];
    __syncthreads();

    int col = tid;
    float w[25];
    #pragma unroll
    for (int k = 0; k < 25; k++) w[k] = s_wd[k];
    float bias = __ldg(&bD[c]);

    float acc[16];
    const float* ab = g_attn + chan + y0 * 256 + col;
    #pragma unroll
    for (int r = 0; r < 16; r++) acc[r] = bias + ab[r * 256];

    #pragma unroll
    for (int rr = 0; rr < 20; rr++) {
        float xv[5];
        #pragma unroll
        for (int dx = 0; dx < 5; dx++) xv[dx] = st[rr * 264 + col + dx];
        #pragma unroll
        for (int dy = 0; dy < 5; dy++) {
            int r = rr - dy;
            if (r >= 0 && r < 16) {
                #pragma unroll
                for (int dx = 0; dx < 5; dx++)
                    acc[r] = fmaf(xv[dx], w[dy * 5 + dx], acc[r]);
            }
        }
    }

    float* db = Dp + chan + y0 * 256 + col;
    #pragma unroll
    for (int r = 0; r < 16; r++)
        db[r * 256] = acc[r];
}

// ---------------------------------------------------------------------------
extern "C" void kernel_launch(void* const* d_in, const int* in_sizes, int n_in,
                              void* d_out, int out_size) {
    const float* vision     = (const float*)d_in[0];
    const float* ass_vision = (const float*)d_in[1];
    const float* wv   = (const float*)d_in[2];
    const float* bv   = (const float*)d_in[3];
    const float* wav  = (const float*)d_in[4];
    const float* bav  = (const float*)d_in[5];
    const float* wqk  = (const float*)d_in[6];
    const float* bqk  = (const float*)d_in[7];
    // d_in[8..9]: waqk/baqk dead (reference bug: aaw unused, ass_attn_out = attn_out)
    const float* wdw  = (const float*)d_in[10];
    const float* bdw  = (const float*)d_in[11];
    const float* wdwa = (const float*)d_in[12];
    const float* bdwa = (const float*)d_in[13];
    const float* wp   = (const float*)d_in[14];
    const float* bp   = (const float*)d_in[15];
    const float* wpa  = (const float*)d_in[16];
    const float* bpa  = (const float*)d_in[17];
    const float* mw1  = (const float*)d_in[18];
    const float* mb1  = (const float*)d_in[19];
    const float* mw2  = (const float*)d_in[20];
    const float* mb2  = (const float*)d_in[21];
    float* out = (float*)d_out;

    float *pV, *paV, *pQ, *pK;
    cudaGetSymbolAddress((void**)&pV,  g_V);
    cudaGetSymbolAddress((void**)&paV, g_aV);
    cudaGetSymbolAddress((void**)&pQ,  g_Q);
    cudaGetSymbolAddress((void**)&pK,  g_K);

    const int SMEM_DW = 5312 * 4;    // 21248
    cudaFuncSetAttribute(conv3_kernel, cudaFuncAttributeMaxDynamicSharedMemorySize, SM_TOTAL);
    cudaFuncSetAttribute(conv_kernel,  cudaFuncAttributeMaxDynamicSharedMemorySize, SM_TOTAL);
    cudaFuncSetAttribute(attn_kernel,  cudaFuncAttributeMaxDynamicSharedMemorySize, SMEM_ATTN);
    cudaFuncSetAttribute(dwz_kernel,   cudaFuncAttributeMaxDynamicSharedMemorySize, SMEM_DW);

    // one-time stream/event infrastructure (host-side, no device memory)
    static cudaStream_t s2 = nullptr;
    static cudaEvent_t evFork = nullptr, evAttn = nullptr, evEnd = nullptr;
    if (!s2) {
        cudaStreamCreateWithFlags(&s2, cudaStreamNonBlocking);
        cudaEventCreateWithFlags(&evFork, cudaEventDisableTiming);
        cudaEventCreateWithFlags(&evAttn, cudaEventDisableTiming);
        cudaEventCreateWithFlags(&evEnd,  cudaEventDisableTiming);
    }

    // fork: s2 starts from the capture-stream front
    cudaEventRecord(evFork, 0);
    cudaStreamWaitEvent(s2, evFork, 0);

    // ---- s2 chain: jaV (independent) ----
    ConvJob jaV = { ass_vision, wav, bav, paV, 1.0f };
    conv_kernel<<<2048, 256, SM_TOTAL, s2>>>(jaV);

    // ---- main chain: bias -> conv3 (V,Q,K) -> attn ----
    bias_kernel<<<16, 256>>>(mw1, mb1, mw2, mb2);
    conv3_kernel<<<2048, 256, SM_TOTAL>>>(vision, wv, bv, wqk, bqk);
    attn_kernel<<<4096, 384, SMEM_ATTN>>>();
    cudaEventRecord(evAttn, 0);

    // ---- s2 chain continues: dw1 (aV + attn -> g_K) -> P1 ----
    cudaStreamWaitEvent(s2, evAttn, 0);
    dwz_kernel<<<6144, 256, SMEM_DW, s2>>>(paV, wdwa, bdwa, pK);
    ConvJob jP1 = { pK, wpa, bpa, out + NPIX, 1.0f };
    conv_kernel<<<2048, 256, SM_TOTAL, s2>>>(jP1);
    cudaEventRecord(evEnd, s2);

    // ---- main chain: dw0 (V + attn -> g_Q) -> P0 ----
    dwz_kernel<<<6144, 256, SMEM_DW>>>(pV, wdw, bdw, pQ);
    ConvJob jP0 = { pQ, wp, bp, out, 1.0f };
    conv_kernel<<<2048, 256, SM_TOTAL>>>(jP0);

    // join s2 back into the capture stream
    cudaStreamWaitEvent(0, evEnd, 0);
}

// round 16
// speedup vs baseline: 1.0939x; 1.0939x over previous
#include <cuda_runtime.h>
#include <math.h>

#define HW   65536
#define IMG  6291456          // 96*65536
#define NPIX 25165824         // 4*96*65536
#define SCALE 0.17677669529663687f

typedef unsigned long long ull;

static __device__ __align__(16) float g_V[NPIX];
static __device__ __align__(16) float g_aV[NPIX];
static __device__ __align__(16) float g_Q[NPIX];
static __device__ __align__(16) float g_K[NPIX];
static __device__ __align__(16) float g_attn[NPIX];
static __device__ __align__(16) float g_bias[3 * 64 * 64];

// ---- packed helpers ---------------------------------------------------------
__device__ __forceinline__ float2 upk(ull v) {
    float2 f; asm("mov.b64 {%0, %1}, %2;" : "=f"(f.x), "=f"(f.y) : "l"(v)); return f;
}

// ---- mma.sync helpers -------------------------------------------------------
__device__ __forceinline__ unsigned smem_u32(const void* p) {
    unsigned a;
    asm("{ .reg .u64 t; cvta.to.shared.u64 t, %1; cvt.u32.u64 %0, t; }" : "=r"(a) : "l"(p));
    return a;
}
__device__ __forceinline__ void ldsm4(unsigned* r, unsigned addr) {
    asm volatile("ldmatrix.sync.aligned.m8n8.x4.shared.b16 {%0,%1,%2,%3}, [%4];"
                 : "=r"(r[0]), "=r"(r[1]), "=r"(r[2]), "=r"(r[3]) : "r"(addr));
}
__device__ __forceinline__ void mma_bf16(float* c, const unsigned* a, unsigned b0, unsigned b1) {
    asm volatile(
        "mma.sync.aligned.m16n8k16.row.col.f32.bf16.bf16.f32 "
        "{%0,%1,%2,%3}, {%4,%5,%6,%7}, {%8,%9}, {%0,%1,%2,%3};"
        : "+f"(c[0]), "+f"(c[1]), "+f"(c[2]), "+f"(c[3])
        : "r"(a[0]), "r"(a[1]), "r"(a[2]), "r"(a[3]), "r"(b0), "r"(b1));
}
// pack 2 floats -> bf16x2 {lo=v0, hi=v1}
__device__ __forceinline__ unsigned cvt2(float v0, float v1) {
    unsigned r; asm("cvt.rn.bf16x2.f32 %0, %1, %2;" : "=r"(r) : "f"(v1), "f"(v0)); return r;
}

// conv swizzled smem byte offsets: row stride 384 B, 16B-window XOR by (row&7)
__device__ __forceinline__ int physA(int px, int kb) { return px * 384 + (kb ^ ((px & 7) << 4)); }
__device__ __forceinline__ int physB(int o,  int kb) { return o  * 384 + (kb ^ ((o  & 7) << 4)); }

#define SM_A 0
#define SM_B 49152
#define SM_BIAS 86016
#define SM_TOTAL 87424

// ---------------------------------------------------------------------------
// K1: relative-position bias MLP
// ---------------------------------------------------------------------------
__device__ __forceinline__ float sgnlog(int d) {
    float l = log1pf(fabsf((float)d));
    return d < 0 ? -l : l;
}

__global__ void bias_kernel(const float* __restrict__ mw1, const float* __restrict__ mb1,
                            const float* __restrict__ mw2, const float* __restrict__ mb2) {
    int t = blockIdx.x * 256 + threadIdx.x;
    if (t >= 4096) return;
    int i = t >> 6, j = t & 63;
    float r0 = sgnlog((i >> 3) - (j >> 3));
    float r1 = sgnlog((i & 7) - (j & 7));
    float a0 = 0.f, a1 = 0.f, a2 = 0.f;
    for (int h = 0; h < 256; h++) {
        float hid = fmaf(r0, mw1[h], fmaf(r1, mw1[256 + h], mb1[h]));
        hid = fmaxf(hid, 0.f);
        a0 = fmaf(hid, mw2[h * 3 + 0], a0);
        a1 = fmaf(hid, mw2[h * 3 + 1], a1);
        a2 = fmaf(hid, mw2[h * 3 + 2], a2);
    }
    g_bias[t]        = a0 + mb2[0];
    g_bias[4096 + t] = a1 + mb2[1];
    g_bias[8192 + t] = a2 + mb2[2];
}

// ---------------------------------------------------------------------------
// Shared conv building blocks (mma.sync bf16 split-2) — proven (R9+)
// ---------------------------------------------------------------------------
__device__ __forceinline__ void conv_a_convert(char* raw, const float* inb, int wid, int lane) {
    int c2 = lane >> 3, pxl = lane & 7;
    #pragma unroll 4
    for (int it = 0; it < 24; it++) {
        int g = it * 8 + wid;
        int po = g & 15, cq = g >> 4;
        int c = cq * 8 + c2 * 2;
        int px = po * 8 + pxl;
        float v0 = inb[c * HW + px];
        float v1 = inb[(c + 1) * HW + px];
        unsigned hi = cvt2(v0, v1);
        float h0 = __uint_as_float(hi << 16);
        float h1 = __uint_as_float(hi & 0xffff0000u);
        unsigned lo = cvt2(v0 - h0, v1 - h1);
        *(unsigned*)(raw + SM_A + physA(px, c * 2))       = hi;
        *(unsigned*)(raw + SM_A + physA(px, 192 + c * 2)) = lo;
    }
}

__device__ __forceinline__ void conv_b_convert(char* raw, const float* w, int tid) {
    for (int l = tid; l < 4608; l += 256) {
        int o = l / 48, cp = l - (l / 48) * 48;
        int c = cp << 1;
        float2 wv = upk(*(const ull*)(w + o * 96 + c));
        unsigned hi = cvt2(wv.x, wv.y);
        float h0 = __uint_as_float(hi << 16);
        float h1 = __uint_as_float(hi & 0xffff0000u);
        unsigned lo = cvt2(wv.x - h0, wv.y - h1);
        *(unsigned*)(raw + SM_B + physB(o, c * 2))       = hi;
        *(unsigned*)(raw + SM_B + physB(o, 192 + c * 2)) = lo;
    }
}

__device__ __forceinline__ void conv_mma_epi(
    char* raw, const float* s_bias_p, float* outb, float scl,
    int wid, int lane)
{
    unsigned sA32 = smem_u32(raw + SM_A);
    unsigned sB32 = smem_u32(raw + SM_B);
    int wm = wid >> 1, wn = wid & 1;
    int gr = lane & 7, gi = lane >> 3;
    int swz = gr << 4;
    int kextA = (gi >> 1) << 4;
    int kextB = (gi & 1) << 4;
    int aRow[2], bRow[3];
    #pragma unroll
    for (int tm = 0; tm < 2; tm++)
        aRow[tm] = (wm * 32 + tm * 16 + gr + (gi & 1) * 8) * 384;
    #pragma unroll
    for (int tp = 0; tp < 3; tp++)
        bRow[tp] = (wn * 48 + tp * 16 + gr + (gi >> 1) * 8) * 384;

    float c[2][6][4];
    #pragma unroll
    for (int tm = 0; tm < 2; tm++)
        #pragma unroll
        for (int tn = 0; tn < 6; tn++)
            #pragma unroll
            for (int q = 0; q < 4; q++) c[tm][tn][q] = 0.f;

    #pragma unroll
    for (int t = 0; t < 3; t++) {
        int kaB = (t == 2) ? 192 : 0;
        int kbB = (t == 1) ? 192 : 0;
        #pragma unroll
        for (int ks = 0; ks < 6; ks++) {
            unsigned aF[2][4], bF[3][4];
            int ka = kaB + ks * 32;
            int kb = kbB + ks * 32;
            #pragma unroll
            for (int tm = 0; tm < 2; tm++)
                ldsm4(aF[tm], sA32 + aRow[tm] + ((ka + kextA) ^ swz));
            #pragma unroll
            for (int tp = 0; tp < 3; tp++)
                ldsm4(bF[tp], sB32 + bRow[tp] + ((kb + kextB) ^ swz));
            #pragma unroll
            for (int tm = 0; tm < 2; tm++)
                #pragma unroll
                for (int tn = 0; tn < 6; tn++) {
                    int tp = tn >> 1, r0 = (tn & 1) * 2;
                    mma_bf16(c[tm][tn], aF[tm], bF[tp][r0], bF[tp][r0 + 1]);
                }
        }
    }
    __syncthreads();

    int pr = lane >> 2, oc = (lane & 3) * 2;
    #pragma unroll
    for (int tm = 0; tm < 2; tm++) {
        int pxr = wm * 32 + tm * 16 + pr;
        #pragma unroll
        for (int tn = 0; tn < 6; tn++) {
            int o0 = wn * 48 + tn * 8 + oc;
            float b0 = s_bias_p[o0], b1 = s_bias_p[o0 + 1];
            outb[o0 * HW + pxr]            = (c[tm][tn][0] + b0) * scl;
            outb[(o0 + 1) * HW + pxr]      = (c[tm][tn][1] + b1) * scl;
            outb[o0 * HW + pxr + 8]        = (c[tm][tn][2] + b0) * scl;
            outb[(o0 + 1) * HW + pxr + 8]  = (c[tm][tn][3] + b1) * scl;
        }
    }
}

// ---------------------------------------------------------------------------
// K2a: phased V/Q/K conv1x1 — one A conversion, three B phases. grid 2048.
// ---------------------------------------------------------------------------
__global__ __launch_bounds__(256, 2)
void conv3_kernel(const float* __restrict__ vision,
                  const float* __restrict__ wv,  const float* __restrict__ bv,
                  const float* __restrict__ wqk, const float* __restrict__ bqk) {
    extern __shared__ __align__(16) char raw[];
    float* s_bias = (float*)(raw + SM_BIAS);

    int tid = threadIdx.x;
    int wid = tid >> 5, lane = tid & 31;
    int bx = blockIdx.x;
    int b = bx >> 9, px0 = (bx & 511) << 7;
    const float* inb = vision + b * IMG + px0;
    int gbase = b * IMG + px0;

    if (tid < 96)        s_bias[tid]        = bv[tid];
    else if (tid < 192)  s_bias[tid]        = bqk[tid - 96];
    if (tid < 96)        s_bias[192 + tid]  = bqk[96 + tid];

    conv_a_convert(raw, inb, wid, lane);

    conv_b_convert(raw, wv, tid);
    __syncthreads();
    conv_mma_epi(raw, s_bias, g_V + gbase, 1.0f, wid, lane);

    conv_b_convert(raw, wqk, tid);
    __syncthreads();
    conv_mma_epi(raw, s_bias + 96, g_Q + gbase, SCALE, wid, lane);

    conv_b_convert(raw, wqk + 9216, tid);
    __syncthreads();
    conv_mma_epi(raw, s_bias + 192, g_K + gbase, 1.0f, wid, lane);
}

// ---------------------------------------------------------------------------
// K2b: generic single-job conv1x1.
// ---------------------------------------------------------------------------
struct ConvJob { const float* in; const float* w; const float* bias; float* out; float scale; };

__global__ __launch_bounds__(256, 2)
void conv_kernel(ConvJob j) {
    extern __shared__ __align__(16) char raw[];
    float* s_bias = (float*)(raw + SM_BIAS);

    int tid = threadIdx.x;
    int wid = tid >> 5, lane = tid & 31;
    int bx = blockIdx.x;
    int b = bx >> 9, px0 = (bx & 511) << 7;
    const float* inb = j.in + b * IMG + px0;

    if (tid < 96) s_bias[tid] = j.bias[tid];
    conv_a_convert(raw, inb, wid, lane);
    conv_b_convert(raw, j.w, tid);
    __syncthreads();
    conv_mma_epi(raw, s_bias, j.out + b * IMG + px0, j.scale, wid, lane);
}

// ---------------------------------------------------------------------------
// K3: window attention via mma.sync bf16 split-2.
// Block = 384 thr = 3 heads x 4 warps; warp owns a 16-row S strip.
// smem per head: Q [64 rows][32hi|32lo bf16]=8KB, K same 8KB,
//                V^T [32 d][64hi|64lo bf16]=8KB.  Total 73728 B.
// S = Qs*K^T (3 terms) + bias; softmax in C-fragments (quad shfl);
// P fragments = cvt2 of S accumulators (C layout == A layout, no shuffles);
// O = P*V (hi*hi + lo*hi + hi*lo), scaled by 1/rowsum at epilogue.
// ---------------------------------------------------------------------------
#define AQ_B 0
#define AK_B 24576
#define AV_B 49152
#define SMEM_ATTN 73728

__global__ __launch_bounds__(384, 2)
void attn_kernel() {
    extern __shared__ __align__(16) char rawc[];

    int tid = threadIdx.x;
    int blk = blockIdx.x;
    int b = blk >> 10, wy = (blk >> 5) & 31, wx = blk & 31;
    int pixoff = b * IMG + wy * 2048 + wx * 8;

    // ---- pass A: Q,K n-major rows (row n: 32 hi bf16 @0..63, 32 lo @64..127) ----
    for (int l = tid; l < 3072; l += 384) {
        int hh = l >> 10;
        int r = l & 1023;
        int n = r & 63, d = ((r >> 6) & 15) << 1;
        int ga = pixoff + (hh * 32 + d) * HW + (n >> 3) * 256 + (n & 7);
        int rowb = hh * 8192 + n * 128;
        int swz = (n & 7) << 4;
        float q0 = g_Q[ga], q1 = g_Q[ga + HW];
        unsigned qh = cvt2(q0, q1);
        *(unsigned*)(rawc + AQ_B + rowb + ((d * 2) ^ swz)) = qh;
        float qh0 = __uint_as_float(qh << 16), qh1 = __uint_as_float(qh & 0xffff0000u);
        *(unsigned*)(rawc + AQ_B + rowb + ((64 + d * 2) ^ swz)) = cvt2(q0 - qh0, q1 - qh1);
        float k0 = g_K[ga], k1 = g_K[ga + HW];
        unsigned kh = cvt2(k0, k1);
        *(unsigned*)(rawc + AK_B + rowb + ((d * 2) ^ swz)) = kh;
        float kh0 = __uint_as_float(kh << 16), kh1 = __uint_as_float(kh & 0xffff0000u);
        *(unsigned*)(rawc + AK_B + rowb + ((64 + d * 2) ^ swz)) = cvt2(k0 - kh0, k1 - kh1);
    }
    // ---- pass B: V transposed d-major rows (row d: 64 hi @0..127, 64 lo @128..255) ----
    for (int l = tid; l < 3072; l += 384) {
        int hh = l >> 10;
        int r = l & 1023;
        int d = r >> 5, n2 = r & 31;
        int ga = pixoff + (hh * 32 + d) * HW + (n2 >> 2) * 256 + (n2 & 3) * 2;
        float2 v = upk(*(const ull*)(g_V + ga));
        int rowb = hh * 8192 + d * 256;
        int swz = (d & 7) << 4;
        unsigned vh = cvt2(v.x, v.y);
        *(unsigned*)(rawc + AV_B + rowb + ((n2 * 4) ^ swz)) = vh;
        float vh0 = __uint_as_float(vh << 16), vh1 = __uint_as_float(vh & 0xffff0000u);
        *(unsigned*)(rawc + AV_B + rowb + 128 + ((n2 * 4) ^ swz)) = cvt2(v.x - vh0, v.y - vh1);
    }
    __syncthreads();

    int wid = tid >> 5, lane = tid & 31;
    int h = wid >> 2, w = wid & 3;
    int gr = lane & 7, gi = lane >> 3;
    int g = lane >> 2, tig = lane & 3;
    int swzA = gr << 4;
    int kextA = (gi >> 1) << 4;
    int kextB = (gi & 1) << 4;
    unsigned sQ = smem_u32(rawc + AQ_B) + h * 8192;
    unsigned sK = smem_u32(rawc + AK_B) + h * 8192;
    unsigned sV = smem_u32(rawc + AV_B) + h * 8192;

    // ---- Q fragments: 4 chunk offsets {0,32,64,96} B = {hi k0, hi k16, lo k0, lo k16} ----
    unsigned aQrow = sQ + (w * 16 + gr + (gi & 1) * 8) * 128;
    unsigned aF[4][4];
    #pragma unroll
    for (int c4 = 0; c4 < 4; c4++)
        ldsm4(aF[c4], aQrow + ((c4 * 32 + kextA) ^ swzA));

    // ---- S mainloop: 4 n-groups x (4 K-chunk frags, 12 mma) ----
    float cS[8][4];
    #pragma unroll
    for (int t = 0; t < 8; t++)
        #pragma unroll
        for (int q = 0; q < 4; q++) cS[t][q] = 0.f;

    #pragma unroll
    for (int ng = 0; ng < 4; ng++) {
        unsigned bRow = sK + (ng * 16 + gr + (gi >> 1) * 8) * 128;
        unsigned bF[4][4];
        #pragma unroll
        for (int c4 = 0; c4 < 4; c4++)
            ldsm4(bF[c4], bRow + ((c4 * 32 + kextB) ^ swzA));
        #pragma unroll
        for (int t3 = 0; t3 < 3; t3++) {
            int ai = (t3 == 2) ? 2 : 0;
            int bi = (t3 == 1) ? 2 : 0;
            #pragma unroll
            for (int kc = 0; kc < 2; kc++)
                #pragma unroll
                for (int sub = 0; sub < 2; sub++)
                    mma_bf16(cS[2 * ng + sub], aF[ai + kc],
                             bF[bi + kc][2 * sub], bF[bi + kc][2 * sub + 1]);
        }
    }

    // ---- bias + softmax in fragment layout ----
    int n0 = w * 16 + g;
    {
        const float* bb = g_bias + h * 4096;
        #pragma unroll
        for (int t = 0; t < 8; t++) {
            float2 b0 = upk(*(const ull*)(bb + n0 * 64 + 8 * t + 2 * tig));
            float2 b1 = upk(*(const ull*)(bb + (n0 + 8) * 64 + 8 * t + 2 * tig));
            cS[t][0] += b0.x; cS[t][1] += b0.y;
            cS[t][2] += b1.x; cS[t][3] += b1.y;
        }
    }
    float mx0 = -1e30f, mx1 = -1e30f;
    #pragma unroll
    for (int t = 0; t < 8; t++) {
        mx0 = fmaxf(mx0, fmaxf(cS[t][0], cS[t][1]));
        mx1 = fmaxf(mx1, fmaxf(cS[t][2], cS[t][3]));
    }
    mx0 = fmaxf(mx0, __shfl_xor_sync(0xffffffffu, mx0, 1));
    mx0 = fmaxf(mx0, __shfl_xor_sync(0xffffffffu, mx0, 2));
    mx1 = fmaxf(mx1, __shfl_xor_sync(0xffffffffu, mx1, 1));
    mx1 = fmaxf(mx1, __shfl_xor_sync(0xffffffffu, mx1, 2));
    float s0 = 0.f, s1 = 0.f;
    #pragma unroll
    for (int t = 0; t < 8; t++) {
        cS[t][0] = __expf(cS[t][0] - mx0);
        cS[t][1] = __expf(cS[t][1] - mx0);
        cS[t][2] = __expf(cS[t][2] - mx1);
        cS[t][3] = __expf(cS[t][3] - mx1);
        s0 += cS[t][0] + cS[t][1];
        s1 += cS[t][2] + cS[t][3];
    }
    s0 += __shfl_xor_sync(0xffffffffu, s0, 1);
    s0 += __shfl_xor_sync(0xffffffffu, s0, 2);
    s1 += __shfl_xor_sync(0xffffffffu, s1, 1);
    s1 += __shfl_xor_sync(0xffffffffu, s1, 2);
    float rinv0 = 1.f / s0, rinv1 = 1.f / s1;

    // ---- P fragments (C layout == A layout for adjacent tile pairs) ----
    unsigned pHi[4][4], pLo[4][4];
    #pragma unroll
    for (int tp = 0; tp < 4; tp++) {
        #pragma unroll
        for (int q = 0; q < 4; q++) {
            int te = 2 * tp + (q >> 1);
            int r0 = (q & 1) * 2;
            float v0 = cS[te][r0], v1 = cS[te][r0 + 1];
            unsigned hi = cvt2(v0, v1);
            pHi[tp][q] = hi;
            float h0 = __uint_as_float(hi << 16), h1 = __uint_as_float(hi & 0xffff0000u);
            pLo[tp][q] = cvt2(v0 - h0, v1 - h1);
        }
    }
    // reorder: pX[tp] = {rows g klo, rows g+8 klo, rows g khi, rows g+8 khi}
    //          built as {te=2tp q0, q1, te=2tp+1 q0, q1} == {a0,a1,a2,a3}  ✓

    // ---- PV mainloop ----
    float cO[4][4];
    #pragma unroll
    for (int t = 0; t < 4; t++)
        #pragma unroll
        for (int q = 0; q < 4; q++) cO[t][q] = 0.f;

    #pragma unroll
    for (int u = 0; u < 2; u++) {
        unsigned bRow = sV + (u * 16 + gr + (gi >> 1) * 8) * 256;
        #pragma unroll
        for (int kc = 0; kc < 4; kc++) {
            unsigned bH[4];
            ldsm4(bH, bRow + ((kc * 32 + kextB) ^ swzA));
            #pragma unroll
            for (int sub = 0; sub < 2; sub++) {
                mma_bf16(cO[2 * u + sub], pHi[kc], bH[2 * sub], bH[2 * sub + 1]);
                mma_bf16(cO[2 * u + sub], pLo[kc], bH[2 * sub], bH[2 * sub + 1]);
            }
            unsigned bL[4];
            ldsm4(bL, bRow + 128 + ((kc * 32 + kextB) ^ swzA));
            #pragma unroll
            for (int sub = 0; sub < 2; sub++)
                mma_bf16(cO[2 * u + sub], pHi[kc], bL[2 * sub], bL[2 * sub + 1]);
        }
    }

    // ---- epilogue: rows n0, n0+8; d = 8*nt + 2*tig ----
    int pixn0 = pixoff + ((n0 >> 3) << 8) + (n0 & 7);
    int pixn8 = pixoff + (((n0 + 8) >> 3) << 8) + ((n0 + 8) & 7);
    #pragma unroll
    for (int nt = 0; nt < 4; nt++) {
        int d0 = h * 32 + 8 * nt + 2 * tig;
        g_attn[pixn0 + d0 * HW]       = cO[nt][0] * rinv0;
        g_attn[pixn0 + (d0 + 1) * HW] = cO[nt][1] * rinv0;
        g_attn[pixn8 + d0 * HW]       = cO[nt][2] * rinv1;
        g_attn[pixn8 + (d0 + 1) * HW] = cO[nt][3] * rinv1;
    }
}

// ---------------------------------------------------------------------------
// K4: single-z depthwise 5x5 + bias + attn -> D. grid 6144 per z.
// ---------------------------------------------------------------------------
__global__ __launch_bounds__(256)
void dwz_kernel(const float* __restrict__ Vp, const float* __restrict__ wD,
                const float* __restrict__ bD, float* __restrict__ Dp) {
    extern __shared__ float st[];
    float* s_wd = st + 5280;

    int bx = blockIdx.x;
    int yt = bx & 15;
    int v = bx >> 4;
    int c = v % 96, b = v / 96;
    int y0 = yt << 4;
    int tid = threadIdx.x;
    int chan = b * IMG + c * HW;
    const float* Vc = Vp + chan;

    for (int l = tid; l < 5200; l += 256) {
        int r = l / 260, q = l - r * 260;
        int yy = y0 + r - 2; yy = yy < 0 ? -yy : (yy > 255 ? 510 - yy : yy);
        int xx = q - 2;      xx = xx < 0 ? -xx : (xx > 255 ? 510 - xx : xx);
        st[r * 264 + q] = Vc[yy * 256 + xx];
    }
    if (tid < 25) s_wd[tid] = wD[c * 25 + tid];
    __syncthreads();

    int col = tid;
    float w[25];
    #pragma unroll
    for (int k = 0; k < 25; k++) w[k] = s_wd[k];
    float bias = __ldg(&bD[c]);

    float acc[16];
    const float* ab = g_attn + chan + y0 * 256 + col;
    #pragma unroll
    for (int r = 0; r < 16; r++) acc[r] = bias + ab[r * 256];

    #pragma unroll
    for (int rr = 0; rr < 20; rr++) {
        float xv[5];
        #pragma unroll
        for (int dx = 0; dx < 5; dx++) xv[dx] = st[rr * 264 + col + dx];
        #pragma unroll
        for (int dy = 0; dy < 5; dy++) {
            int r = rr - dy;
            if (r >= 0 && r < 16) {
                #pragma unroll
                for (int dx = 0; dx < 5; dx++)
                    acc[r] = fmaf(xv[dx], w[dy * 5 + dx], acc[r]);
            }
        }
    }

    float* db = Dp + chan + y0 * 256 + col;
    #pragma unroll
    for (int r = 0; r < 16; r++)
        db[r * 256] = acc[r];
}

// ---------------------------------------------------------------------------
extern "C" void kernel_launch(void* const* d_in, const int* in_sizes, int n_in,
                              void* d_out, int out_size) {
    const float* vision     = (const float*)d_in[0];
    const float* ass_vision = (const float*)d_in[1];
    const float* wv   = (const float*)d_in[2];
    const float* bv   = (const float*)d_in[3];
    const float* wav  = (const float*)d_in[4];
    const float* bav  = (const float*)d_in[5];
    const float* wqk  = (const float*)d_in[6];
    const float* bqk  = (const float*)d_in[7];
    // d_in[8..9]: waqk/baqk dead (reference bug: aaw unused, ass_attn_out = attn_out)
    const float* wdw  = (const float*)d_in[10];
    const float* bdw  = (const float*)d_in[11];
    const float* wdwa = (const float*)d_in[12];
    const float* bdwa = (const float*)d_in[13];
    const float* wp   = (const float*)d_in[14];
    const float* bp   = (const float*)d_in[15];
    const float* wpa  = (const float*)d_in[16];
    const float* bpa  = (const float*)d_in[17];
    const float* mw1  = (const float*)d_in[18];
    const float* mb1  = (const float*)d_in[19];
    const float* mw2  = (const float*)d_in[20];
    const float* mb2  = (const float*)d_in[21];
    float* out = (float*)d_out;

    float *pV, *paV, *pQ, *pK;
    cudaGetSymbolAddress((void**)&pV,  g_V);
    cudaGetSymbolAddress((void**)&paV, g_aV);
    cudaGetSymbolAddress((void**)&pQ,  g_Q);
    cudaGetSymbolAddress((void**)&pK,  g_K);

    const int SMEM_DW = 5312 * 4;
    cudaFuncSetAttribute(conv3_kernel, cudaFuncAttributeMaxDynamicSharedMemorySize, SM_TOTAL);
    cudaFuncSetAttribute(conv_kernel,  cudaFuncAttributeMaxDynamicSharedMemorySize, SM_TOTAL);
    cudaFuncSetAttribute(attn_kernel,  cudaFuncAttributeMaxDynamicSharedMemorySize, SMEM_ATTN);
    cudaFuncSetAttribute(dwz_kernel,   cudaFuncAttributeMaxDynamicSharedMemorySize, SMEM_DW);

    static cudaStream_t s2 = nullptr;
    static cudaEvent_t evFork = nullptr, evAttn = nullptr, evEnd = nullptr;
    if (!s2) {
        cudaStreamCreateWithFlags(&s2, cudaStreamNonBlocking);
        cudaEventCreateWithFlags(&evFork, cudaEventDisableTiming);
        cudaEventCreateWithFlags(&evAttn, cudaEventDisableTiming);
        cudaEventCreateWithFlags(&evEnd,  cudaEventDisableTiming);
    }

    cudaEventRecord(evFork, 0);
    cudaStreamWaitEvent(s2, evFork, 0);

    // s2: jaV (independent)
    ConvJob jaV = { ass_vision, wav, bav, paV, 1.0f };
    conv_kernel<<<2048, 256, SM_TOTAL, s2>>>(jaV);

    // main: bias -> conv3 (V,Q,K) -> attn
    bias_kernel<<<16, 256>>>(mw1, mb1, mw2, mb2);
    conv3_kernel<<<2048, 256, SM_TOTAL>>>(vision, wv, bv, wqk, bqk);
    attn_kernel<<<4096, 384, SMEM_ATTN>>>();
    cudaEventRecord(evAttn, 0);

    // s2: dw1 -> P1
    cudaStreamWaitEvent(s2, evAttn, 0);
    dwz_kernel<<<6144, 256, SMEM_DW, s2>>>(paV, wdwa, bdwa, pK);
    ConvJob jP1 = { pK, wpa, bpa, out + NPIX, 1.0f };
    conv_kernel<<<2048, 256, SM_TOTAL, s2>>>(jP1);
    cudaEventRecord(evEnd, s2);

    // main: dw0 -> P0
    dwz_kernel<<<6144, 256, SMEM_DW>>>(pV, wdw, bdw, pQ);
    ConvJob jP0 = { pQ, wp, bp, out, 1.0f };
    conv_kernel<<<2048, 256, SM_TOTAL>>>(jP0);

    cudaStreamWaitEvent(0, evEnd, 0);
}

// round 17
// speedup vs baseline: 1.2495x; 1.1422x over previous
#include <cuda_runtime.h>
#include <math.h>

#define HW   65536
#define IMG  6291456          // 96*65536
#define NPIX 25165824         // 4*96*65536
#define SCALE 0.17677669529663687f

typedef unsigned long long ull;

static __device__ __align__(16) float g_V[NPIX];
static __device__ __align__(16) float g_aV[NPIX];
static __device__ __align__(16) float g_Q[NPIX];
static __device__ __align__(16) float g_K[NPIX];
static __device__ __align__(16) float g_attn[NPIX];
static __device__ __align__(16) float g_bias[3 * 64 * 64];
// pre-split, pre-swizzled bf16 weights: 6 matrices x 36864 B
static __device__ __align__(16) unsigned g_WB[6 * 9216];

// ---- packed helpers ---------------------------------------------------------
__device__ __forceinline__ float2 upk(ull v) {
    float2 f; asm("mov.b64 {%0, %1}, %2;" : "=f"(f.x), "=f"(f.y) : "l"(v)); return f;
}

// ---- mma.sync helpers -------------------------------------------------------
__device__ __forceinline__ unsigned smem_u32(const void* p) {
    unsigned a;
    asm("{ .reg .u64 t; cvta.to.shared.u64 t, %1; cvt.u32.u64 %0, t; }" : "=r"(a) : "l"(p));
    return a;
}
__device__ __forceinline__ void ldsm4(unsigned* r, unsigned addr) {
    asm volatile("ldmatrix.sync.aligned.m8n8.x4.shared.b16 {%0,%1,%2,%3}, [%4];"
                 : "=r"(r[0]), "=r"(r[1]), "=r"(r[2]), "=r"(r[3]) : "r"(addr));
}
__device__ __forceinline__ void mma_bf16(float* c, const unsigned* a, unsigned b0, unsigned b1) {
    asm volatile(
        "mma.sync.aligned.m16n8k16.row.col.f32.bf16.bf16.f32 "
        "{%0,%1,%2,%3}, {%4,%5,%6,%7}, {%8,%9}, {%0,%1,%2,%3};"
        : "+f"(c[0]), "+f"(c[1]), "+f"(c[2]), "+f"(c[3])
        : "r"(a[0]), "r"(a[1]), "r"(a[2]), "r"(a[3]), "r"(b0), "r"(b1));
}
// pack 2 floats -> bf16x2 {lo=v0, hi=v1}
__device__ __forceinline__ unsigned cvt2(float v0, float v1) {
    unsigned r; asm("cvt.rn.bf16x2.f32 %0, %1, %2;" : "=r"(r) : "f"(v1), "f"(v0)); return r;
}

// conv swizzled smem byte offsets: row stride 384 B, 16B-window XOR by (row&7)
__device__ __forceinline__ int physA(int px, int kb) { return px * 384 + (kb ^ ((px & 7) << 4)); }
__device__ __forceinline__ int physB(int o,  int kb) { return o  * 384 + (kb ^ ((o  & 7) << 4)); }

#define SM_A 0
#define SM_B 49152
#define SM_BIAS 86016
#define SM_TOTAL 87424

// ---------------------------------------------------------------------------
// K0: weight prep — split fp32 weights into bf16 hi/lo, pre-swizzled smem image.
// m: 0=wv 1=wqk(Q) 2=wqk(K) 3=wav 4=wp 5=wpa
// ---------------------------------------------------------------------------
__global__ void prep_kernel(const float* __restrict__ w0, const float* __restrict__ w1,
                            const float* __restrict__ w2, const float* __restrict__ w3,
                            const float* __restrict__ w4, const float* __restrict__ w5) {
    int t = blockIdx.x * 256 + threadIdx.x;
    if (t >= 27648) return;
    int m = t / 4608;
    int r = t - m * 4608;
    int o = r / 48, cp = r - (r / 48) * 48;
    int c = cp * 2;
    const float* w = (m == 0) ? w0 : (m == 1) ? w1 : (m == 2) ? w2
                   : (m == 3) ? w3 : (m == 4) ? w4 : w5;
    float2 wv = upk(*(const ull*)(w + o * 96 + c));
    unsigned hi = cvt2(wv.x, wv.y);
    float h0 = __uint_as_float(hi << 16);
    float h1 = __uint_as_float(hi & 0xffff0000u);
    unsigned lo = cvt2(wv.x - h0, wv.y - h1);
    char* base = (char*)g_WB + m * 36864;
    *(unsigned*)(base + physB(o, c * 2))       = hi;
    *(unsigned*)(base + physB(o, 192 + c * 2)) = lo;
}

// ---------------------------------------------------------------------------
// K1: relative-position bias MLP
// ---------------------------------------------------------------------------
__device__ __forceinline__ float sgnlog(int d) {
    float l = log1pf(fabsf((float)d));
    return d < 0 ? -l : l;
}

__global__ void bias_kernel(const float* __restrict__ mw1, const float* __restrict__ mb1,
                            const float* __restrict__ mw2, const float* __restrict__ mb2) {
    int t = blockIdx.x * 256 + threadIdx.x;
    if (t >= 4096) return;
    int i = t >> 6, j = t & 63;
    float r0 = sgnlog((i >> 3) - (j >> 3));
    float r1 = sgnlog((i & 7) - (j & 7));
    float a0 = 0.f, a1 = 0.f, a2 = 0.f;
    for (int h = 0; h < 256; h++) {
        float hid = fmaf(r0, mw1[h], fmaf(r1, mw1[256 + h], mb1[h]));
        hid = fmaxf(hid, 0.f);
        a0 = fmaf(hid, mw2[h * 3 + 0], a0);
        a1 = fmaf(hid, mw2[h * 3 + 1], a1);
        a2 = fmaf(hid, mw2[h * 3 + 2], a2);
    }
    g_bias[t]        = a0 + mb2[0];
    g_bias[4096 + t] = a1 + mb2[1];
    g_bias[8192 + t] = a2 + mb2[2];
}

// ---------------------------------------------------------------------------
// Conv building blocks (mma.sync bf16 split-2)
// ---------------------------------------------------------------------------
__device__ __forceinline__ void conv_a_convert(char* raw, const float* inb, int wid, int lane) {
    int c2 = lane >> 3, pxl = lane & 7;
    #pragma unroll 4
    for (int it = 0; it < 24; it++) {
        int g = it * 8 + wid;
        int po = g & 15, cq = g >> 4;
        int c = cq * 8 + c2 * 2;
        int px = po * 8 + pxl;
        float v0 = inb[c * HW + px];
        float v1 = inb[(c + 1) * HW + px];
        unsigned hi = cvt2(v0, v1);
        float h0 = __uint_as_float(hi << 16);
        float h1 = __uint_as_float(hi & 0xffff0000u);
        unsigned lo = cvt2(v0 - h0, v1 - h1);
        *(unsigned*)(raw + SM_A + physA(px, c * 2))       = hi;
        *(unsigned*)(raw + SM_A + physA(px, 192 + c * 2)) = lo;
    }
}

// B tile: straight coalesced copy of the pre-swizzled image
__device__ __forceinline__ void conv_b_load(char* raw, const ull* __restrict__ src, int tid) {
    ull* dst = (ull*)(raw + SM_B);
    #pragma unroll
    for (int l = tid; l < 4608; l += 256) dst[l] = src[l];
}

__device__ __forceinline__ void conv_mma_epi(
    char* raw, const float* s_bias_p, float* outb, float scl,
    int wid, int lane)
{
    unsigned sA32 = smem_u32(raw + SM_A);
    unsigned sB32 = smem_u32(raw + SM_B);
    int wm = wid >> 1, wn = wid & 1;
    int gr = lane & 7, gi = lane >> 3;
    int swz = gr << 4;
    int kextA = (gi >> 1) << 4;
    int kextB = (gi & 1) << 4;
    int aRow[2], bRow[3];
    #pragma unroll
    for (int tm = 0; tm < 2; tm++)
        aRow[tm] = (wm * 32 + tm * 16 + gr + (gi & 1) * 8) * 384;
    #pragma unroll
    for (int tp = 0; tp < 3; tp++)
        bRow[tp] = (wn * 48 + tp * 16 + gr + (gi >> 1) * 8) * 384;

    float c[2][6][4];
    #pragma unroll
    for (int tm = 0; tm < 2; tm++)
        #pragma unroll
        for (int tn = 0; tn < 6; tn++)
            #pragma unroll
            for (int q = 0; q < 4; q++) c[tm][tn][q] = 0.f;

    #pragma unroll
    for (int t = 0; t < 3; t++) {
        int kaB = (t == 2) ? 192 : 0;
        int kbB = (t == 1) ? 192 : 0;
        #pragma unroll
        for (int ks = 0; ks < 6; ks++) {
            unsigned aF[2][4], bF[3][4];
            int ka = kaB + ks * 32;
            int kb = kbB + ks * 32;
            #pragma unroll
            for (int tm = 0; tm < 2; tm++)
                ldsm4(aF[tm], sA32 + aRow[tm] + ((ka + kextA) ^ swz));
            #pragma unroll
            for (int tp = 0; tp < 3; tp++)
                ldsm4(bF[tp], sB32 + bRow[tp] + ((kb + kextB) ^ swz));
            #pragma unroll
            for (int tm = 0; tm < 2; tm++)
                #pragma unroll
                for (int tn = 0; tn < 6; tn++) {
                    int tp = tn >> 1, r0 = (tn & 1) * 2;
                    mma_bf16(c[tm][tn], aF[tm], bF[tp][r0], bF[tp][r0 + 1]);
                }
        }
    }
    __syncthreads();

    int pr = lane >> 2, oc = (lane & 3) * 2;
    #pragma unroll
    for (int tm = 0; tm < 2; tm++) {
        int pxr = wm * 32 + tm * 16 + pr;
        #pragma unroll
        for (int tn = 0; tn < 6; tn++) {
            int o0 = wn * 48 + tn * 8 + oc;
            float b0 = s_bias_p[o0], b1 = s_bias_p[o0 + 1];
            outb[o0 * HW + pxr]            = (c[tm][tn][0] + b0) * scl;
            outb[(o0 + 1) * HW + pxr]      = (c[tm][tn][1] + b1) * scl;
            outb[o0 * HW + pxr + 8]        = (c[tm][tn][2] + b0) * scl;
            outb[(o0 + 1) * HW + pxr + 8]  = (c[tm][tn][3] + b1) * scl;
        }
    }
}

// ---------------------------------------------------------------------------
// K2a: per-batch phased V/Q/K conv1x1. grid 512.
// ---------------------------------------------------------------------------
__global__ __launch_bounds__(256, 2)
void conv3_kernel(const float* __restrict__ vision,
                  const ull* __restrict__ wb0, const ull* __restrict__ wb1,
                  const ull* __restrict__ wb2,
                  const float* __restrict__ bv, const float* __restrict__ bqk, int b) {
    extern __shared__ __align__(16) char raw[];
    float* s_bias = (float*)(raw + SM_BIAS);

    int tid = threadIdx.x;
    int wid = tid >> 5, lane = tid & 31;
    int px0 = blockIdx.x << 7;
    const float* inb = vision + b * IMG + px0;
    int gbase = b * IMG + px0;

    if (tid < 96)        s_bias[tid]        = bv[tid];
    else if (tid < 192)  s_bias[tid]        = bqk[tid - 96];
    if (tid < 96)        s_bias[192 + tid]  = bqk[96 + tid];

    conv_a_convert(raw, inb, wid, lane);

    conv_b_load(raw, wb0, tid);
    __syncthreads();
    conv_mma_epi(raw, s_bias, g_V + gbase, 1.0f, wid, lane);

    conv_b_load(raw, wb1, tid);
    __syncthreads();
    conv_mma_epi(raw, s_bias + 96, g_Q + gbase, SCALE, wid, lane);

    conv_b_load(raw, wb2, tid);
    __syncthreads();
    conv_mma_epi(raw, s_bias + 192, g_K + gbase, 1.0f, wid, lane);
}

// ---------------------------------------------------------------------------
// K2b: generic conv1x1; grid (512,1,nb), batch = b_base + blockIdx.z.
// ---------------------------------------------------------------------------
struct ConvJob { const float* in; const ull* wb; const float* bias; float* out; float scale; };

__global__ __launch_bounds__(256, 2)
void conv_kernel(ConvJob j, int b_base) {
    extern __shared__ __align__(16) char raw[];
    float* s_bias = (float*)(raw + SM_BIAS);

    int tid = threadIdx.x;
    int wid = tid >> 5, lane = tid & 31;
    int b = b_base + blockIdx.z;
    int px0 = blockIdx.x << 7;
    const float* inb = j.in + b * IMG + px0;

    if (tid < 96) s_bias[tid] = j.bias[tid];
    conv_a_convert(raw, inb, wid, lane);
    conv_b_load(raw, j.wb, tid);
    __syncthreads();
    conv_mma_epi(raw, s_bias, j.out + b * IMG + px0, j.scale, wid, lane);
}

// ---------------------------------------------------------------------------
// K3: window attention via mma.sync bf16 split-2 (proven R16). Per batch: grid 1024.
// ---------------------------------------------------------------------------
#define AQ_B 0
#define AK_B 24576
#define AV_B 49152
#define SMEM_ATTN 73728

__global__ __launch_bounds__(384, 2)
void attn_kernel(int b) {
    extern __shared__ __align__(16) char rawc[];

    int tid = threadIdx.x;
    int blk = blockIdx.x;
    int wy = (blk >> 5) & 31, wx = blk & 31;
    int pixoff = b * IMG + wy * 2048 + wx * 8;

    // pass A: Q,K n-major rows (row n: 32 hi bf16 @0..63, 32 lo @64..127)
    for (int l = tid; l < 3072; l += 384) {
        int hh = l >> 10;
        int r = l & 1023;
        int n = r & 63, d = ((r >> 6) & 15) << 1;
        int ga = pixoff + (hh * 32 + d) * HW + (n >> 3) * 256 + (n & 7);
        int rowb = hh * 8192 + n * 128;
        int swz = (n & 7) << 4;
        float q0 = g_Q[ga], q1 = g_Q[ga + HW];
        unsigned qh = cvt2(q0, q1);
        *(unsigned*)(rawc + AQ_B + rowb + ((d * 2) ^ swz)) = qh;
        float qh0 = __uint_as_float(qh << 16), qh1 = __uint_as_float(qh & 0xffff0000u);
        *(unsigned*)(rawc + AQ_B + rowb + ((64 + d * 2) ^ swz)) = cvt2(q0 - qh0, q1 - qh1);
        float k0 = g_K[ga], k1 = g_K[ga + HW];
        unsigned kh = cvt2(k0, k1);
        *(unsigned*)(rawc + AK_B + rowb + ((d * 2) ^ swz)) = kh;
        float kh0 = __uint_as_float(kh << 16), kh1 = __uint_as_float(kh & 0xffff0000u);
        *(unsigned*)(rawc + AK_B + rowb + ((64 + d * 2) ^ swz)) = cvt2(k0 - kh0, k1 - kh1);
    }
    // pass B: V transposed d-major rows (row d: 64 hi @0..127, 64 lo @128..255)
    for (int l = tid; l < 3072; l += 384) {
        int hh = l >> 10;
        int r = l & 1023;
        int d = r >> 5, n2 = r & 31;
        int ga = pixoff + (hh * 32 + d) * HW + (n2 >> 2) * 256 + (n2 & 3) * 2;
        float2 v = upk(*(const ull*)(g_V + ga));
        int rowb = hh * 8192 + d * 256;
        int swz = (d & 7) << 4;
        unsigned vh = cvt2(v.x, v.y);
        *(unsigned*)(rawc + AV_B + rowb + ((n2 * 4) ^ swz)) = vh;
        float vh0 = __uint_as_float(vh << 16), vh1 = __uint_as_float(vh & 0xffff0000u);
        *(unsigned*)(rawc + AV_B + rowb + 128 + ((n2 * 4) ^ swz)) = cvt2(v.x - vh0, v.y - vh1);
    }
    __syncthreads();

    int wid = tid >> 5, lane = tid & 31;
    int h = wid >> 2, w = wid & 3;
    int gr = lane & 7, gi = lane >> 3;
    int g = lane >> 2, tig = lane & 3;
    int swzA = gr << 4;
    int kextA = (gi >> 1) << 4;
    int kextB = (gi & 1) << 4;
    unsigned sQ = smem_u32(rawc + AQ_B) + h * 8192;
    unsigned sK = smem_u32(rawc + AK_B) + h * 8192;
    unsigned sV = smem_u32(rawc + AV_B) + h * 8192;

    unsigned aQrow = sQ + (w * 16 + gr + (gi & 1) * 8) * 128;
    unsigned aF[4][4];
    #pragma unroll
    for (int c4 = 0; c4 < 4; c4++)
        ldsm4(aF[c4], aQrow + ((c4 * 32 + kextA) ^ swzA));

    float cS[8][4];
    #pragma unroll
    for (int t = 0; t < 8; t++)
        #pragma unroll
        for (int q = 0; q < 4; q++) cS[t][q] = 0.f;

    #pragma unroll
    for (int ng = 0; ng < 4; ng++) {
        unsigned bRow = sK + (ng * 16 + gr + (gi >> 1) * 8) * 128;
        unsigned bF[4][4];
        #pragma unroll
        for (int c4 = 0; c4 < 4; c4++)
            ldsm4(bF[c4], bRow + ((c4 * 32 + kextB) ^ swzA));
        #pragma unroll
        for (int t3 = 0; t3 < 3; t3++) {
            int ai = (t3 == 2) ? 2 : 0;
            int bi = (t3 == 1) ? 2 : 0;
            #pragma unroll
            for (int kc = 0; kc < 2; kc++)
                #pragma unroll
                for (int sub = 0; sub < 2; sub++)
                    mma_bf16(cS[2 * ng + sub], aF[ai + kc],
                             bF[bi + kc][2 * sub], bF[bi + kc][2 * sub + 1]);
        }
    }

    int n0 = w * 16 + g;
    {
        const float* bb = g_bias + h * 4096;
        #pragma unroll
        for (int t = 0; t < 8; t++) {
            float2 b0 = upk(*(const ull*)(bb + n0 * 64 + 8 * t + 2 * tig));
            float2 b1 = upk(*(const ull*)(bb + (n0 + 8) * 64 + 8 * t + 2 * tig));
            cS[t][0] += b0.x; cS[t][1] += b0.y;
            cS[t][2] += b1.x; cS[t][3] += b1.y;
        }
    }
    float mx0 = -1e30f, mx1 = -1e30f;
    #pragma unroll
    for (int t = 0; t < 8; t++) {
        mx0 = fmaxf(mx0, fmaxf(cS[t][0], cS[t][1]));
        mx1 = fmaxf(mx1, fmaxf(cS[t][2], cS[t][3]));
    }
    mx0 = fmaxf(mx0, __shfl_xor_sync(0xffffffffu, mx0, 1));
    mx0 = fmaxf(mx0, __shfl_xor_sync(0xffffffffu, mx0, 2));
    mx1 = fmaxf(mx1, __shfl_xor_sync(0xffffffffu, mx1, 1));
    mx1 = fmaxf(mx1, __shfl_xor_sync(0xffffffffu, mx1, 2));
    float s0 = 0.f, s1 = 0.f;
    #pragma unroll
    for (int t = 0; t < 8; t++) {
        cS[t][0] = __expf(cS[t][0] - mx0);
        cS[t][1] = __expf(cS[t][1] - mx0);
        cS[t][2] = __expf(cS[t][2] - mx1);
        cS[t][3] = __expf(cS[t][3] - mx1);
        s0 += cS[t][0] + cS[t][1];
        s1 += cS[t][2] + cS[t][3];
    }
    s0 += __shfl_xor_sync(0xffffffffu, s0, 1);
    s0 += __shfl_xor_sync(0xffffffffu, s0, 2);
    s1 += __shfl_xor_sync(0xffffffffu, s1, 1);
    s1 += __shfl_xor_sync(0xffffffffu, s1, 2);
    float rinv0 = 1.f / s0, rinv1 = 1.f / s1;

    unsigned pHi[4][4], pLo[4][4];
    #pragma unroll
    for (int tp = 0; tp < 4; tp++) {
        #pragma unroll
        for (int q = 0; q < 4; q++) {
            int te = 2 * tp + (q >> 1);
            int r0 = (q & 1) * 2;
            float v0 = cS[te][r0], v1 = cS[te][r0 + 1];
            unsigned hi = cvt2(v0, v1);
            pHi[tp][q] = hi;
            float h0 = __uint_as_float(hi << 16), h1 = __uint_as_float(hi & 0xffff0000u);
            pLo[tp][q] = cvt2(v0 - h0, v1 - h1);
        }
    }

    float cO[4][4];
    #pragma unroll
    for (int t = 0; t < 4; t++)
        #pragma unroll
        for (int q = 0; q < 4; q++) cO[t][q] = 0.f;

    #pragma unroll
    for (int u = 0; u < 2; u++) {
        unsigned bRow = sV + (u * 16 + gr + (gi >> 1) * 8) * 256;
        #pragma unroll
        for (int kc = 0; kc < 4; kc++) {
            unsigned bH[4];
            ldsm4(bH, bRow + ((kc * 32 + kextB) ^ swzA));
            #pragma unroll
            for (int sub = 0; sub < 2; sub++) {
                mma_bf16(cO[2 * u + sub], pHi[kc], bH[2 * sub], bH[2 * sub + 1]);
                mma_bf16(cO[2 * u + sub], pLo[kc], bH[2 * sub], bH[2 * sub + 1]);
            }
            unsigned bL[4];
            ldsm4(bL, bRow + 128 + ((kc * 32 + kextB) ^ swzA));
            #pragma unroll
            for (int sub = 0; sub < 2; sub++)
                mma_bf16(cO[2 * u + sub], pHi[kc], bL[2 * sub], bL[2 * sub + 1]);
        }
    }

    int pixn0 = pixoff + ((n0 >> 3) << 8) + (n0 & 7);
    int pixn8 = pixoff + (((n0 + 8) >> 3) << 8) + ((n0 + 8) & 7);
    #pragma unroll
    for (int nt = 0; nt < 4; nt++) {
        int d0 = h * 32 + 8 * nt + 2 * tig;
        g_attn[pixn0 + d0 * HW]       = cO[nt][0] * rinv0;
        g_attn[pixn0 + (d0 + 1) * HW] = cO[nt][1] * rinv0;
        g_attn[pixn8 + d0 * HW]       = cO[nt][2] * rinv1;
        g_attn[pixn8 + (d0 + 1) * HW] = cO[nt][3] * rinv1;
    }
}

// ---------------------------------------------------------------------------
// K4: per-batch single-z depthwise 5x5 + bias + attn -> D. grid 1536.
// ---------------------------------------------------------------------------
__global__ __launch_bounds__(256)
void dwz_kernel(const float* __restrict__ Vp, const float* __restrict__ wD,
                const float* __restrict__ bD, float* __restrict__ Dp, int b) {
    extern __shared__ float st[];
    float* s_wd = st + 5280;

    int bx = blockIdx.x;               // 1536 = 16 * 96
    int yt = bx & 15;
    int c = bx >> 4;
    int y0 = yt << 4;
    int tid = threadIdx.x;
    int chan = b * IMG + c * HW;
    const float* Vc = Vp + chan;

    for (int l = tid; l < 5200; l += 256) {
        int r = l / 260, q = l - r * 260;
        int yy = y0 + r - 2; yy = yy < 0 ? -yy : (yy > 255 ? 510 - yy : yy);
        int xx = q - 2;      xx = xx < 0 ? -xx : (xx > 255 ? 510 - xx : xx);
        st[r * 264 + q] = Vc[yy * 256 + xx];
    }
    if (tid < 25) s_wd[tid] = wD[c * 25 + tid];
    __syncthreads();

    int col = tid;
    float w[25];
    #pragma unroll
    for (int k = 0; k < 25; k++) w[k] = s_wd[k];
    float bias = __ldg(&bD[c]);

    float acc[16];
    const float* ab = g_attn + chan + y0 * 256 + col;
    #pragma unroll
    for (int r = 0; r < 16; r++) acc[r] = bias + ab[r * 256];

    #pragma unroll
    for (int rr = 0; rr < 20; rr++) {
        float xv[5];
        #pragma unroll
        for (int dx = 0; dx < 5; dx++) xv[dx] = st[rr * 264 + col + dx];
        #pragma unroll
        for (int dy = 0; dy < 5; dy++) {
            int r = rr - dy;
            if (r >= 0 && r < 16) {
                #pragma unroll
                for (int dx = 0; dx < 5; dx++)
                    acc[r] = fmaf(xv[dx], w[dy * 5 + dx], acc[r]);
            }
        }
    }

    float* db = Dp + chan + y0 * 256 + col;
    #pragma unroll
    for (int r = 0; r < 16; r++)
        db[r * 256] = acc[r];
}

// ---------------------------------------------------------------------------
extern "C" void kernel_launch(void* const* d_in, const int* in_sizes, int n_in,
                              void* d_out, int out_size) {
    const float* vision     = (const float*)d_in[0];
    const float* ass_vision = (const float*)d_in[1];
    const float* wv   = (const float*)d_in[2];
    const float* bv   = (const float*)d_in[3];
    const float* wav  = (const float*)d_in[4];
    const float* bav  = (const float*)d_in[5];
    const float* wqk  = (const float*)d_in[6];
    const float* bqk  = (const float*)d_in[7];
    // d_in[8..9]: waqk/baqk dead (reference bug: aaw unused, ass_attn_out = attn_out)
    const float* wdw  = (const float*)d_in[10];
    const float* bdw  = (const float*)d_in[11];
    const float* wdwa = (const float*)d_in[12];
    const float* bdwa = (const float*)d_in[13];
    const float* wp   = (const float*)d_in[14];
    const float* bp   = (const float*)d_in[15];
    const float* wpa  = (const float*)d_in[16];
    const float* bpa  = (const float*)d_in[17];
    const float* mw1  = (const float*)d_in[18];
    const float* mb1  = (const float*)d_in[19];
    const float* mw2  = (const float*)d_in[20];
    const float* mb2  = (const float*)d_in[21];
    float* out = (float*)d_out;

    float *pV, *paV, *pQ, *pK;
    void* pWBv;
    cudaGetSymbolAddress((void**)&pV,  g_V);
    cudaGetSymbolAddress((void**)&paV, g_aV);
    cudaGetSymbolAddress((void**)&pQ,  g_Q);
    cudaGetSymbolAddress((void**)&pK,  g_K);
    cudaGetSymbolAddress(&pWBv, g_WB);
    const ull* wb = (const ull*)pWBv;

    const int SMEM_DW = 5312 * 4;
    cudaFuncSetAttribute(conv3_kernel, cudaFuncAttributeMaxDynamicSharedMemorySize, SM_TOTAL);
    cudaFuncSetAttribute(conv_kernel,  cudaFuncAttributeMaxDynamicSharedMemorySize, SM_TOTAL);
    cudaFuncSetAttribute(attn_kernel,  cudaFuncAttributeMaxDynamicSharedMemorySize, SMEM_ATTN);
    cudaFuncSetAttribute(dwz_kernel,   cudaFuncAttributeMaxDynamicSharedMemorySize, SMEM_DW);

    // one-time stream/event infrastructure (host-side, no device memory)
    static cudaStream_t sAttn = nullptr, sD0 = nullptr, sD1 = nullptr;
    static cudaEvent_t evF, evP, evC[4], evA[4], evD0, evD1;
    if (!sAttn) {
        cudaStreamCreateWithFlags(&sAttn, cudaStreamNonBlocking);
        cudaStreamCreateWithFlags(&sD0,   cudaStreamNonBlocking);
        cudaStreamCreateWithFlags(&sD1,   cudaStreamNonBlocking);
        cudaEventCreateWithFlags(&evF, cudaEventDisableTiming);
        cudaEventCreateWithFlags(&evP, cudaEventDisableTiming);
        for (int i = 0; i < 4; i++) {
            cudaEventCreateWithFlags(&evC[i], cudaEventDisableTiming);
            cudaEventCreateWithFlags(&evA[i], cudaEventDisableTiming);
        }
        cudaEventCreateWithFlags(&evD0, cudaEventDisableTiming);
        cudaEventCreateWithFlags(&evD1, cudaEventDisableTiming);
    }

    // fork all side streams from the capture-stream front
    cudaEventRecord(evF, 0);
    cudaStreamWaitEvent(sAttn, evF, 0);
    cudaStreamWaitEvent(sD0, evF, 0);
    cudaStreamWaitEvent(sD1, evF, 0);

    // prologue: weight prep + bias (stream 0)
    prep_kernel<<<108, 256>>>(wv, wqk, wqk + 9216, wav, wp, wpa);
    bias_kernel<<<16, 256>>>(mw1, mb1, mw2, mb2);
    cudaEventRecord(evP, 0);

    // jaV (full batch) on sD1 — needs prepped weights
    cudaStreamWaitEvent(sD1, evP, 0);
    ConvJob jaV = { ass_vision, wb + 3 * 4608, bav, paV, 1.0f };
    conv_kernel<<<dim3(512, 1, 4), 256, SM_TOTAL, sD1>>>(jaV, 0);

    // per-batch pipeline
    for (int b = 0; b < 4; b++) {
        conv3_kernel<<<512, 256, SM_TOTAL>>>(vision, wb, wb + 4608, wb + 2 * 4608,
                                             bv, bqk, b);
        cudaEventRecord(evC[b], 0);

        cudaStreamWaitEvent(sAttn, evC[b], 0);
        attn_kernel<<<1024, 384, SMEM_ATTN, sAttn>>>(b);
        cudaEventRecord(evA[b], sAttn);

        cudaStreamWaitEvent(sD0, evA[b], 0);
        dwz_kernel<<<1536, 256, SMEM_DW, sD0>>>(pV, wdw, bdw, pQ, b);
        ConvJob jP0 = { pQ, wb + 4 * 4608, bp, out, 1.0f };
        conv_kernel<<<dim3(512, 1, 1), 256, SM_TOTAL, sD0>>>(jP0, b);

        cudaStreamWaitEvent(sD1, evA[b], 0);
        dwz_kernel<<<1536, 256, SMEM_DW, sD1>>>(paV, wdwa, bdwa, pK, b);
        ConvJob jP1 = { pK, wb + 5 * 4608, bpa, out + NPIX, 1.0f };
        conv_kernel<<<dim3(512, 1, 1), 256, SM_TOTAL, sD1>>>(jP1, b);
    }

    // join everything back into the capture stream
    cudaEventRecord(evD0, sD0);
    cudaEventRecord(evD1, sD1);
    cudaStreamWaitEvent(0, evD0, 0);
    cudaStreamWaitEvent(0, evD1, 0);
}